// round 11
// baseline (speedup 1.0000x reference)
#include <cuda_runtime.h>
#include <cuda_fp16.h>
#include <math.h>
#include <stdint.h>

#define Bb   2
#define Ss   2048
#define Hh   4096
#define NHh  32
#define HDd  128
#define KVHh 8
#define Mtot (Bb*Ss)          // 4096
#define NQKV 6144             // 4096 q + 2048 kv

// ---------------- scratch (allocation-free) ----------------
__device__ __half g_qkvh[Mtot*NQKV];          // fused QKV GEMM output (fp16)
__device__ __half g_hsh[Mtot*Hh];             // hs fp16
__device__ __half g_wt[NQKV*Hh];              // [Wq^T ; Wkv^T] fp16 [N][K]
__device__ __half g_wdt[Hh*Hh];               // Wd^T fp16
__device__ __half g_qh[Bb*Ss*NHh*HDd];        // post-RoPE q, pre-scaled, fp16
__device__ __half g_kh[Bb*Ss*KVHh*HDd];       // post-RoPE k, fp16
__device__ __half g_vt[Bb*KVHh*HDd*Ss];       // V transposed [b][kvh][d][s] fp16
__device__ __half g_ctxh[Mtot*Hh];            // attention output fp16
__device__ float  g_cos[Ss*64];
__device__ float  g_sin[Ss*64];

// ---------------- helpers ----------------
__device__ __forceinline__ uint32_t smem_u32(const void* p) {
    uint32_t a;
    asm("{ .reg .u64 t; cvta.to.shared.u64 t, %1; cvt.u32.u64 %0, t; }" : "=r"(a) : "l"(p));
    return a;
}
#define CP_ASYNC16(dst_u32, src_ptr) \
    asm volatile("cp.async.cg.shared.global [%0], [%1], 16;" :: "r"(dst_u32), "l"(src_ptr) : "memory")
#define CP_COMMIT() asm volatile("cp.async.commit_group;" ::: "memory")
#define CP_WAIT(n)  asm volatile("cp.async.wait_group %0;" :: "n"(n) : "memory")

#define LDSM4(r0, r1, r2, r3, addr) \
    asm volatile("ldmatrix.sync.aligned.m8n8.x4.shared.b16 {%0,%1,%2,%3}, [%4];" \
                 : "=r"(r0), "=r"(r1), "=r"(r2), "=r"(r3) : "r"(addr))

__device__ __forceinline__ void mma_f16_16n8k16(float* c, const uint32_t* a, const uint32_t* b) {
    asm volatile(
        "mma.sync.aligned.m16n8k16.row.col.f32.f16.f16.f32 "
        "{%0,%1,%2,%3}, {%4,%5,%6,%7}, {%8,%9}, {%0,%1,%2,%3};"
        : "+f"(c[0]), "+f"(c[1]), "+f"(c[2]), "+f"(c[3])
        : "r"(a[0]), "r"(a[1]), "r"(a[2]), "r"(a[3]), "r"(b[0]), "r"(b[1]));
}

// ---------------------------------------------------------------------------
// prep1: rope tables + hs->fp16 + three weight transposes, one launch.
// ---------------------------------------------------------------------------
#define NB_TABLE 512
#define NB_CVT   16384
#define NB_TRQ   16384
#define NB_TRKV  8192
#define NB_TRD   16384
#define NB_PREP1 (NB_TABLE + NB_CVT + NB_TRQ + NB_TRKV + NB_TRD)

__global__ void __launch_bounds__(256) prep1_kernel(
    const float* __restrict__ hs, const float* __restrict__ Wq,
    const float* __restrict__ Wkv, const float* __restrict__ Wd)
{
    __shared__ float t[32][33];
    int blk = blockIdx.x;
    const int tid = threadIdx.x;

    if (blk < NB_TABLE) {                      // rope cos/sin table
        int idx = blk * 256 + tid;
        int s = idx >> 6, j = idx & 63;
        double invf = exp(-(double)j * (log(10000.0) / 64.0));
        float th = (float)s * (float)invf;
        g_cos[idx] = (float)cos((double)th);
        g_sin[idx] = (float)sin((double)th);
        return;
    }
    blk -= NB_TABLE;
    if (blk < NB_CVT) {                        // hs fp32 -> fp16
        int i = blk * 256 + tid;
        float4 v = ((const float4*)hs)[i];
        __half2* d2 = (__half2*)g_hsh;
        d2[i * 2]     = __floats2half2_rn(v.x, v.y);
        d2[i * 2 + 1] = __floats2half2_rn(v.z, v.w);
        return;
    }
    blk -= NB_CVT;

    const float* src; __half* dst; int N; int tix;
    if (blk < NB_TRQ)       { src = Wq;  dst = g_wt;                    N = Hh;   tix = blk; }
    else if ((blk -= NB_TRQ) < NB_TRKV) { src = Wkv; dst = g_wt + (size_t)Hh * Hh; N = 2048; tix = blk; }
    else                    { blk -= NB_TRKV; src = Wd; dst = g_wdt;    N = Hh;   tix = blk; }

    const int K = Hh;
    const int ncols = N / 32;
    const int n0 = (tix % ncols) * 32, k0 = (tix / ncols) * 32;
    const int tx = tid & 31, ty = tid >> 5;
    #pragma unroll
    for (int i = 0; i < 32; i += 8)
        t[ty + i][tx] = src[(size_t)(k0 + ty + i) * N + n0 + tx];
    __syncthreads();
    #pragma unroll
    for (int i = 0; i < 32; i += 8)
        dst[(size_t)(n0 + ty + i) * K + k0 + tx] = __float2half_rn(t[tx][ty + i]);
}

// ---------------------------------------------------------------------------
// prep2: RoPE apply (q pre-scaled) + V transpose, one launch. fp16 source.
// ---------------------------------------------------------------------------
#define NB_ROPE 40960
#define NB_VT   4096
#define NB_PREP2 (NB_ROPE + NB_VT)

__global__ void __launch_bounds__(256) prep2_kernel() {
    __shared__ float t[32][33];
    int blk = blockIdx.x;
    const int tid = threadIdx.x;

    if (blk < NB_ROPE) {                       // RoPE on q and k
        int idx = blk * 256 + tid;
        const float qscale = 0.08838834764831845f;   // 1/sqrt(128)
        int j    = idx & 63;
        int tt   = idx >> 6;
        int head = tt % (NHh + KVHh);
        int row  = tt / (NHh + KVHh);
        int s    = row & (Ss - 1);
        float c  = g_cos[(s << 6) + j];
        float sn = g_sin[(s << 6) + j];
        if (head < NHh) {
            const __half* base = g_qkvh + (size_t)row * NQKV + head * HDd;
            float x1 = __half2float(base[j]), x2 = __half2float(base[j + 64]);
            __half* dst = g_qh + ((size_t)row * NHh + head) * HDd;
            dst[j]      = __float2half_rn((x1 * c - x2 * sn) * qscale);
            dst[j + 64] = __float2half_rn((x2 * c + x1 * sn) * qscale);
        } else {
            int kvh = head - NHh;
            const __half* base = g_qkvh + (size_t)row * NQKV + Hh + kvh * 256;
            float x1 = __half2float(base[j]), x2 = __half2float(base[j + 64]);
            __half* dst = g_kh + ((size_t)row * KVHh + kvh) * HDd;
            dst[j]      = __float2half_rn(x1 * c - x2 * sn);
            dst[j + 64] = __float2half_rn(x2 * c + x1 * sn);
        }
        return;
    }
    blk -= NB_ROPE;                            // V transpose -> g_vt

    int s0 = (blk & 63) * 32;
    int rest = blk >> 6;
    int d0 = (rest & 3) * 32;
    int bk = rest >> 2;                        // b*KVHh + kvh
    int b = bk >> 3, kvh = bk & 7;
    const int tx = tid & 31, ty = tid >> 5;
    const __half* src = g_qkvh + (size_t)(b * Ss) * NQKV + Hh + kvh * 256 + 128;
    #pragma unroll
    for (int i = 0; i < 32; i += 8)
        t[ty + i][tx] = __half2float(src[(size_t)(s0 + ty + i) * NQKV + d0 + tx]);
    __syncthreads();
    __half* dst = g_vt + (size_t)bk * HDd * Ss;
    #pragma unroll
    for (int i = 0; i < 32; i += 8)
        dst[(size_t)(d0 + ty + i) * Ss + s0 + tx] = __float2half_rn(t[tx][ty + i]);
}

// ---------------------------------------------------------------------------
// fp16 mma.sync GEMM: CTA 128x128, 8 warps (2x4) of 64x32 warp tiles,
// BK=32, 5-stage cp.async (deep pipeline), ldmatrix. 102.4KB -> 2 CTAs/SM.
// LDT=40 halves: rows shift 20 banks -> ldmatrix conflict-free.
// Templated output: fp16 (QKV) or fp32 (+bias+residual, dense).
// ---------------------------------------------------------------------------
#define BM 128
#define BN 128
#define BK 32
#define STG 5
#define LDT 40
#define TILEH (BM * LDT)                  // 5120 halves per tile per stage
#define GSMEM_BYTES (STG * 2 * TILEH * 2) // 102400

template <typename OutT>
__global__ void __launch_bounds__(256) gemm_f16_kernel(
    const __half* __restrict__ A, const __half* __restrict__ Bt,
    OutT* __restrict__ C, int N, int K,
    const float* __restrict__ bias, const float* __restrict__ resid)
{
    extern __shared__ __half smh[];
    __half* As = smh;                 // [STG][BM][LDT]
    __half* Bs = smh + STG * TILEH;   // [STG][BN][LDT]
    const uint32_t as_u = smem_u32(As);
    const uint32_t bs_u = smem_u32(Bs);

    const int tid  = threadIdx.x;
    const int bm   = blockIdx.y * BM, bn = blockIdx.x * BN;
    const int warp = tid >> 5, lane = tid & 31;
    const int g    = lane >> 2, t4 = lane & 3;
    const int wm   = (warp & 1) * 64, wn = (warp >> 1) * 32;

    const int a_row = (lane & 7) + 8 * ((lane >> 3) & 1);
    const int a_c8  = (lane >> 4) * 8;
    const int b_row = (lane & 7) + 8 * (lane >> 4);
    const int b_c8  = ((lane >> 3) & 1) * 8;

    const int NC = K / BK;   // 128 chunks

    auto load_stage = [&](int s, int c) {
        const __half* Aptr = A  + (size_t)bm * K + (size_t)c * BK;
        const __half* Bptr = Bt + (size_t)bn * K + (size_t)c * BK;
        #pragma unroll
        for (int i = 0; i < 2; ++i) {     // 128 rows x 4 segs each for A and B
            int idx = tid + i * 256;
            int row = idx >> 2, c8 = idx & 3;
            uint32_t so = (uint32_t)((s * TILEH + row * LDT + c8 * 8) * 2);
            CP_ASYNC16(as_u + so, Aptr + (size_t)row * K + c8 * 8);
            CP_ASYNC16(bs_u + so, Bptr + (size_t)row * K + c8 * 8);
        }
    };

    float acc[4][4][4];
    #pragma unroll
    for (int mi = 0; mi < 4; ++mi)
        #pragma unroll
        for (int ni = 0; ni < 4; ++ni)
            #pragma unroll
            for (int r = 0; r < 4; ++r) acc[mi][ni][r] = 0.f;

    #pragma unroll
    for (int s = 0; s < STG - 1; ++s) { load_stage(s, s); CP_COMMIT(); }

    for (int c = 0; c < NC; ++c) {
        CP_WAIT(STG - 2);
        __syncthreads();
        if (c + STG - 1 < NC) load_stage((c + STG - 1) % STG, c + STG - 1);
        CP_COMMIT();

        const uint32_t a_base = as_u +
            (uint32_t)(((c % STG) * TILEH + (wm + a_row) * LDT + a_c8) * 2);
        const uint32_t b_base = bs_u +
            (uint32_t)(((c % STG) * TILEH + (wn + b_row) * LDT + b_c8) * 2);

        #pragma unroll
        for (int ks = 0; ks < 2; ++ks) {
            uint32_t af[4][4], bf[4][2];
            #pragma unroll
            for (int mi = 0; mi < 4; ++mi)
                LDSM4(af[mi][0], af[mi][1], af[mi][2], af[mi][3],
                      a_base + (uint32_t)(mi * 16 * LDT * 2 + ks * 32));
            #pragma unroll
            for (int nj = 0; nj < 2; ++nj)
                LDSM4(bf[2 * nj][0], bf[2 * nj][1], bf[2 * nj + 1][0], bf[2 * nj + 1][1],
                      b_base + (uint32_t)(nj * 16 * LDT * 2 + ks * 32));
            #pragma unroll
            for (int mi = 0; mi < 4; ++mi)
                #pragma unroll
                for (int ni = 0; ni < 4; ++ni)
                    mma_f16_16n8k16(acc[mi][ni], af[mi], bf[ni]);
        }
    }

    #pragma unroll
    for (int mi = 0; mi < 4; ++mi) {
        #pragma unroll
        for (int half = 0; half < 2; ++half) {
            int row = bm + wm + mi * 16 + g + half * 8;
            OutT* crow = C + (size_t)row * N;
            const float* rrow = resid ? resid + (size_t)row * N : nullptr;
            #pragma unroll
            for (int ni = 0; ni < 4; ++ni) {
                int col = bn + wn + ni * 8 + 2 * t4;
                float v0 = acc[mi][ni][half * 2 + 0];
                float v1 = acc[mi][ni][half * 2 + 1];
                if (bias) { v0 += bias[col]; v1 += bias[col + 1]; }
                if (rrow) { v0 += rrow[col]; v1 += rrow[col + 1]; }
                if constexpr (sizeof(OutT) == 2) {
                    *(__half2*)&crow[col] = __floats2half2_rn(v0, v1);
                } else {
                    *(float2*)&crow[col] = make_float2(v0, v1);
                }
            }
        }
    }
}

// ---------------------------------------------------------------------------
// Flash attention (R7/R10 proven config, heavy-tile-first ordering).
// ---------------------------------------------------------------------------
#define AT_LQ 136
#define AT_LV 72
#define AT_QS  0
#define AT_KS  (64*AT_LQ)
#define AT_VS  (AT_KS + 2*64*AT_LQ)
#define AT_PS  (AT_VS + 2*128*AT_LV)
#define AT_SMEM_HALVES (AT_PS + 64*AT_LV)
#define AT_SMEM_BYTES  (AT_SMEM_HALVES * 2)     // 98304

__global__ void __launch_bounds__(128) attn_f16_kernel() {
    extern __shared__ __half smh[];
    __half* Qs = smh + AT_QS;   // [64][136]
    __half* Ks = smh + AT_KS;   // [2][64][136]
    __half* Vs = smh + AT_VS;   // [2][128][72]
    __half* Ps = smh + AT_PS;   // [64][72]
    const uint32_t qs_u = smem_u32(Qs), ks_u = smem_u32(Ks), vs_u = smem_u32(Vs);
    const uint32_t ps_u = smem_u32(Ps);

    const int tid = threadIdx.x, warp = tid >> 5, lane = tid & 31;
    const int g = lane >> 2, t4 = lane & 3;
    const int qt = gridDim.x - 1 - blockIdx.x;   // heavy tiles start first
    const int h = blockIdx.y, b = blockIdx.z;
    const int kvh = h >> 2;

    const int a_row = (lane & 7) + 8 * ((lane >> 3) & 1);
    const int a_c8  = (lane >> 4) * 8;
    const int b_row = (lane & 7) + 8 * (lane >> 4);
    const int b_c8  = ((lane >> 3) & 1) * 8;

    {
        const __half* qbase = g_qh + ((size_t)(b * Ss + qt * 64) * NHh + h) * HDd;
        #pragma unroll
        for (int i = 0; i < 8; ++i) {
            int lin = tid + i * 128;
            int r = lin >> 4, c8 = (lin & 15) << 3;
            CP_ASYNC16(qs_u + (uint32_t)((r * AT_LQ + c8) * 2),
                       qbase + (size_t)r * (NHh * HDd) + c8);
        }
    }

    auto load_kv = [&](int st, int kt) {
        const __half* kbase = g_kh + ((size_t)(b * Ss + kt * 64) * KVHh + kvh) * HDd;
        #pragma unroll
        for (int i = 0; i < 8; ++i) {
            int lin = tid + i * 128;
            int r = lin >> 4, c8 = (lin & 15) << 3;
            CP_ASYNC16(ks_u + (uint32_t)((st * 64 * AT_LQ + r * AT_LQ + c8) * 2),
                       kbase + (size_t)r * (KVHh * HDd) + c8);
        }
        const __half* vbase = g_vt + (size_t)(b * KVHh + kvh) * HDd * Ss + kt * 64;
        #pragma unroll
        for (int i = 0; i < 8; ++i) {
            int lin = tid + i * 128;
            int r = lin >> 3, c8 = (lin & 7) << 3;
            CP_ASYNC16(vs_u + (uint32_t)((st * 128 * AT_LV + r * AT_LV + c8) * 2),
                       vbase + (size_t)r * Ss + c8);
        }
    };

    float m_i[2], l_i[2];
    m_i[0] = m_i[1] = -INFINITY;
    l_i[0] = l_i[1] = 0.f;
    float o[16][4];
    #pragma unroll
    for (int ni = 0; ni < 16; ++ni)
        #pragma unroll
        for (int r = 0; r < 4; ++r) o[ni][r] = 0.f;

    load_kv(0, 0); CP_COMMIT();

    const uint32_t qa_base = qs_u +
        (uint32_t)(((16 * warp + a_row) * AT_LQ + a_c8) * 2);
    const uint32_t pa_base = ps_u +
        (uint32_t)(((16 * warp + a_row) * AT_LV + a_c8) * 2);

    for (int kt = 0; kt <= qt; ++kt) {
        const int st = kt & 1;
        CP_WAIT(0);
        __syncthreads();
        if (kt < qt) { load_kv(st ^ 1, kt + 1); CP_COMMIT(); }

        float c[8][4];
        #pragma unroll
        for (int ni = 0; ni < 8; ++ni)
            #pragma unroll
            for (int r = 0; r < 4; ++r) c[ni][r] = 0.f;

        const uint32_t kb_base = ks_u +
            (uint32_t)((st * 64 * AT_LQ + b_row * AT_LQ + b_c8) * 2);
        #pragma unroll
        for (int ks = 0; ks < 8; ++ks) {
            uint32_t af[4], bf[8][2];
            LDSM4(af[0], af[1], af[2], af[3], qa_base + (uint32_t)(ks * 32));
            #pragma unroll
            for (int nj = 0; nj < 4; ++nj)
                LDSM4(bf[2 * nj][0], bf[2 * nj][1], bf[2 * nj + 1][0], bf[2 * nj + 1][1],
                      kb_base + (uint32_t)(nj * 16 * AT_LQ * 2 + ks * 32));
            #pragma unroll
            for (int ni = 0; ni < 8; ++ni)
                mma_f16_16n8k16(c[ni], af, bf[ni]);
        }

        if (kt == qt) {
            #pragma unroll
            for (int r = 0; r < 2; ++r) {
                const int rloc = 16 * warp + g + 8 * r;
                #pragma unroll
                for (int ni = 0; ni < 8; ++ni) {
                    const int cloc = ni * 8 + 2 * t4;
                    if (cloc     > rloc) c[ni][2 * r]     = -INFINITY;
                    if (cloc + 1 > rloc) c[ni][2 * r + 1] = -INFINITY;
                }
            }
        }

        #pragma unroll
        for (int r = 0; r < 2; ++r) {
            float mt = -INFINITY;
            #pragma unroll
            for (int ni = 0; ni < 8; ++ni)
                mt = fmaxf(mt, fmaxf(c[ni][2 * r], c[ni][2 * r + 1]));
            mt = fmaxf(mt, __shfl_xor_sync(0xffffffffu, mt, 1));
            mt = fmaxf(mt, __shfl_xor_sync(0xffffffffu, mt, 2));
            const float mn = fmaxf(m_i[r], mt);
            const float corr = __expf(m_i[r] - mn);
            float rs = 0.f;
            #pragma unroll
            for (int ni = 0; ni < 8; ++ni) {
                float p0 = __expf(c[ni][2 * r]     - mn);
                float p1 = __expf(c[ni][2 * r + 1] - mn);
                rs += p0 + p1;
                *(__half2*)&Ps[(16 * warp + g + 8 * r) * AT_LV + ni * 8 + 2 * t4] =
                    __floats2half2_rn(p0, p1);
            }
            rs += __shfl_xor_sync(0xffffffffu, rs, 1);
            rs += __shfl_xor_sync(0xffffffffu, rs, 2);
            l_i[r] = l_i[r] * corr + rs;
            m_i[r] = mn;
            #pragma unroll
            for (int ni = 0; ni < 16; ++ni) {
                o[ni][2 * r]     *= corr;
                o[ni][2 * r + 1] *= corr;
            }
        }
        __syncwarp();

        const uint32_t vb_base = vs_u +
            (uint32_t)((st * 128 * AT_LV + b_row * AT_LV + b_c8) * 2);
        #pragma unroll
        for (int ks = 0; ks < 4; ++ks) {
            uint32_t af[4], bf[16][2];
            LDSM4(af[0], af[1], af[2], af[3], pa_base + (uint32_t)(ks * 32));
            #pragma unroll
            for (int nj = 0; nj < 8; ++nj)
                LDSM4(bf[2 * nj][0], bf[2 * nj][1], bf[2 * nj + 1][0], bf[2 * nj + 1][1],
                      vb_base + (uint32_t)(nj * 16 * AT_LV * 2 + ks * 32));
            #pragma unroll
            for (int ni = 0; ni < 16; ++ni)
                mma_f16_16n8k16(o[ni], af, bf[ni]);
        }
    }

    #pragma unroll
    for (int r = 0; r < 2; ++r) {
        const float inv = 1.f / l_i[r];
        const int row = qt * 64 + 16 * warp + g + 8 * r;
        __half* obase = g_ctxh + (size_t)(b * Ss + row) * Hh + h * HDd;
        #pragma unroll
        for (int ni = 0; ni < 16; ++ni) {
            const int col = ni * 8 + 2 * t4;
            *(__half2*)&obase[col] = __floats2half2_rn(o[ni][2 * r] * inv,
                                                       o[ni][2 * r + 1] * inv);
        }
    }
}

// ---------------------------------------------------------------------------
extern "C" void kernel_launch(void* const* d_in, const int* in_sizes, int n_in,
                              void* d_out, int out_size) {
    const float* hs  = (const float*)d_in[0];
    const float* res = (const float*)d_in[1];
    const float* Wq  = (const float*)d_in[3];
    const float* Wkv = (const float*)d_in[4];
    const float* Wd  = (const float*)d_in[5];
    const float* bd  = (const float*)d_in[6];
    float* out = (float*)d_out;

    __half *qkvh, *hsh, *wt, *wdt, *ctxh;
    cudaGetSymbolAddress((void**)&qkvh, g_qkvh);
    cudaGetSymbolAddress((void**)&hsh,  g_hsh);
    cudaGetSymbolAddress((void**)&wt,   g_wt);
    cudaGetSymbolAddress((void**)&wdt,  g_wdt);
    cudaGetSymbolAddress((void**)&ctxh, g_ctxh);

    cudaFuncSetAttribute(attn_f16_kernel, cudaFuncAttributeMaxDynamicSharedMemorySize, AT_SMEM_BYTES);
    cudaFuncSetAttribute(gemm_f16_kernel<__half>, cudaFuncAttributeMaxDynamicSharedMemorySize, GSMEM_BYTES);
    cudaFuncSetAttribute(gemm_f16_kernel<float>,  cudaFuncAttributeMaxDynamicSharedMemorySize, GSMEM_BYTES);

    // prep 1: rope table + hs fp16 + all weight transposes (one launch)
    prep1_kernel<<<NB_PREP1, 256>>>(hs, Wq, Wkv, Wd);

    // fused QKV projection: C[4096][6144] fp16
    gemm_f16_kernel<__half><<<dim3(NQKV / BN, Mtot / BM), 256, GSMEM_BYTES>>>(
        hsh, wt, qkvh, NQKV, Hh, nullptr, nullptr);

    // prep 2: RoPE apply + V transpose (one launch)
    prep2_kernel<<<NB_PREP2, 256>>>();

    attn_f16_kernel<<<dim3(Ss / 64, NHh, Bb), 128, AT_SMEM_BYTES>>>();

    gemm_f16_kernel<float><<<dim3(Hh / BN, Mtot / BM), 256, GSMEM_BYTES>>>(
        ctxh, wdt, out, Hh, Hh, bd, res);
}

// round 13
// speedup vs baseline: 1.1484x; 1.1484x over previous
#include <cuda_runtime.h>
#include <cuda_fp16.h>
#include <math.h>
#include <stdint.h>

#define Bb   2
#define Ss   2048
#define Hh   4096
#define NHh  32
#define HDd  128
#define KVHh 8
#define Mtot (Bb*Ss)          // 4096
#define NQKV 6144             // 4096 q + 2048 kv

// ---------------- scratch (allocation-free) ----------------
__device__ __half g_qkvh[Mtot*NQKV];          // fused QKV GEMM output (fp16)
__device__ __half g_hsh[Mtot*Hh];             // hs fp16
__device__ __half g_wt[NQKV*Hh];              // [Wq^T ; Wkv^T] fp16 [N][K]
__device__ __half g_wdt[Hh*Hh];               // Wd^T fp16
__device__ __half g_qh[Bb*Ss*NHh*HDd];        // post-RoPE q, pre-scaled, fp16
__device__ __half g_kh[Bb*Ss*KVHh*HDd];       // post-RoPE k, fp16
__device__ __half g_vt[Bb*KVHh*HDd*Ss];       // V transposed [b][kvh][d][s] fp16
__device__ __half g_ctxh[Mtot*Hh];            // attention output fp16
__device__ float  g_cos[Ss*64];
__device__ float  g_sin[Ss*64];

// ---------------- helpers ----------------
__device__ __forceinline__ uint32_t smem_u32(const void* p) {
    uint32_t a;
    asm("{ .reg .u64 t; cvta.to.shared.u64 t, %1; cvt.u32.u64 %0, t; }" : "=r"(a) : "l"(p));
    return a;
}
#define CP_ASYNC16(dst_u32, src_ptr) \
    asm volatile("cp.async.cg.shared.global [%0], [%1], 16;" :: "r"(dst_u32), "l"(src_ptr) : "memory")
#define CP_COMMIT() asm volatile("cp.async.commit_group;" ::: "memory")
#define CP_WAIT(n)  asm volatile("cp.async.wait_group %0;" :: "n"(n) : "memory")

#define LDSM4(r0, r1, r2, r3, addr) \
    asm volatile("ldmatrix.sync.aligned.m8n8.x4.shared.b16 {%0,%1,%2,%3}, [%4];" \
                 : "=r"(r0), "=r"(r1), "=r"(r2), "=r"(r3) : "r"(addr))

__device__ __forceinline__ void mma_f16_16n8k16(float* c, const uint32_t* a, const uint32_t* b) {
    asm volatile(
        "mma.sync.aligned.m16n8k16.row.col.f32.f16.f16.f32 "
        "{%0,%1,%2,%3}, {%4,%5,%6,%7}, {%8,%9}, {%0,%1,%2,%3};"
        : "+f"(c[0]), "+f"(c[1]), "+f"(c[2]), "+f"(c[3])
        : "r"(a[0]), "r"(a[1]), "r"(a[2]), "r"(a[3]), "r"(b[0]), "r"(b[1]));
}

// ---------------------------------------------------------------------------
// prep1: rope tables + hs->fp16 + three weight transposes, one launch.
// ---------------------------------------------------------------------------
#define NB_TABLE 512
#define NB_CVT   16384
#define NB_TRQ   16384
#define NB_TRKV  8192
#define NB_TRD   16384
#define NB_PREP1 (NB_TABLE + NB_CVT + NB_TRQ + NB_TRKV + NB_TRD)

__global__ void __launch_bounds__(256) prep1_kernel(
    const float* __restrict__ hs, const float* __restrict__ Wq,
    const float* __restrict__ Wkv, const float* __restrict__ Wd)
{
    __shared__ float t[32][33];
    int blk = blockIdx.x;
    const int tid = threadIdx.x;

    if (blk < NB_TABLE) {                      // rope cos/sin table
        int idx = blk * 256 + tid;
        int s = idx >> 6, j = idx & 63;
        double invf = exp(-(double)j * (log(10000.0) / 64.0));
        float th = (float)s * (float)invf;
        g_cos[idx] = (float)cos((double)th);
        g_sin[idx] = (float)sin((double)th);
        return;
    }
    blk -= NB_TABLE;
    if (blk < NB_CVT) {                        // hs fp32 -> fp16
        int i = blk * 256 + tid;
        float4 v = ((const float4*)hs)[i];
        __half2* d2 = (__half2*)g_hsh;
        d2[i * 2]     = __floats2half2_rn(v.x, v.y);
        d2[i * 2 + 1] = __floats2half2_rn(v.z, v.w);
        return;
    }
    blk -= NB_CVT;

    const float* src; __half* dst; int N; int tix;
    if (blk < NB_TRQ)       { src = Wq;  dst = g_wt;                    N = Hh;   tix = blk; }
    else if ((blk -= NB_TRQ) < NB_TRKV) { src = Wkv; dst = g_wt + (size_t)Hh * Hh; N = 2048; tix = blk; }
    else                    { blk -= NB_TRKV; src = Wd; dst = g_wdt;    N = Hh;   tix = blk; }

    const int K = Hh;
    const int ncols = N / 32;
    const int n0 = (tix % ncols) * 32, k0 = (tix / ncols) * 32;
    const int tx = tid & 31, ty = tid >> 5;
    #pragma unroll
    for (int i = 0; i < 32; i += 8)
        t[ty + i][tx] = src[(size_t)(k0 + ty + i) * N + n0 + tx];
    __syncthreads();
    #pragma unroll
    for (int i = 0; i < 32; i += 8)
        dst[(size_t)(n0 + ty + i) * K + k0 + tx] = __float2half_rn(t[tx][ty + i]);
}

// ---------------------------------------------------------------------------
// prep2: RoPE apply (q pre-scaled) + V transpose, one launch. fp16 source.
// ---------------------------------------------------------------------------
#define NB_ROPE 40960
#define NB_VT   4096
#define NB_PREP2 (NB_ROPE + NB_VT)

__global__ void __launch_bounds__(256) prep2_kernel() {
    __shared__ float t[32][33];
    int blk = blockIdx.x;
    const int tid = threadIdx.x;

    if (blk < NB_ROPE) {                       // RoPE on q and k
        int idx = blk * 256 + tid;
        const float qscale = 0.08838834764831845f;   // 1/sqrt(128)
        int j    = idx & 63;
        int tt   = idx >> 6;
        int head = tt % (NHh + KVHh);
        int row  = tt / (NHh + KVHh);
        int s    = row & (Ss - 1);
        float c  = g_cos[(s << 6) + j];
        float sn = g_sin[(s << 6) + j];
        if (head < NHh) {
            const __half* base = g_qkvh + (size_t)row * NQKV + head * HDd;
            float x1 = __half2float(base[j]), x2 = __half2float(base[j + 64]);
            __half* dst = g_qh + ((size_t)row * NHh + head) * HDd;
            dst[j]      = __float2half_rn((x1 * c - x2 * sn) * qscale);
            dst[j + 64] = __float2half_rn((x2 * c + x1 * sn) * qscale);
        } else {
            int kvh = head - NHh;
            const __half* base = g_qkvh + (size_t)row * NQKV + Hh + kvh * 256;
            float x1 = __half2float(base[j]), x2 = __half2float(base[j + 64]);
            __half* dst = g_kh + ((size_t)row * KVHh + kvh) * HDd;
            dst[j]      = __float2half_rn(x1 * c - x2 * sn);
            dst[j + 64] = __float2half_rn(x2 * c + x1 * sn);
        }
        return;
    }
    blk -= NB_ROPE;                            // V transpose -> g_vt

    int s0 = (blk & 63) * 32;
    int rest = blk >> 6;
    int d0 = (rest & 3) * 32;
    int bk = rest >> 2;                        // b*KVHh + kvh
    int b = bk >> 3, kvh = bk & 7;
    const int tx = tid & 31, ty = tid >> 5;
    const __half* src = g_qkvh + (size_t)(b * Ss) * NQKV + Hh + kvh * 256 + 128;
    #pragma unroll
    for (int i = 0; i < 32; i += 8)
        t[ty + i][tx] = __half2float(src[(size_t)(s0 + ty + i) * NQKV + d0 + tx]);
    __syncthreads();
    __half* dst = g_vt + (size_t)bk * HDd * Ss;
    #pragma unroll
    for (int i = 0; i < 32; i += 8)
        dst[(size_t)(d0 + ty + i) * Ss + s0 + tx] = __float2half_rn(t[tx][ty + i]);
}

// ---------------------------------------------------------------------------
// fp16 mma.sync GEMM (R10 proven mainloop): CTA 128x128, 8 warps (2x4) of
// 64x32 warp tiles, BK=64, 3-stage cp.async, ldmatrix, LDT=72,
// 110.6KB smem -> 2 CTAs/SM. Templated output (fp16 QKV / fp32 dense).
// ---------------------------------------------------------------------------
#define BM 128
#define BN 128
#define BK 64
#define STG 3
#define LDT 72
#define TILEH (BM * LDT)                  // halves per tile per stage
#define GSMEM_BYTES (STG * 2 * TILEH * 2) // 110592

template <typename OutT>
__global__ void __launch_bounds__(256) gemm_f16_kernel(
    const __half* __restrict__ A, const __half* __restrict__ Bt,
    OutT* __restrict__ C, int N, int K,
    const float* __restrict__ bias, const float* __restrict__ resid)
{
    extern __shared__ __half smh[];
    __half* As = smh;                 // [STG][BM][LDT]
    __half* Bs = smh + STG * TILEH;   // [STG][BN][LDT]
    const uint32_t as_u = smem_u32(As);
    const uint32_t bs_u = smem_u32(Bs);

    const int tid  = threadIdx.x;
    const int bm   = blockIdx.y * BM, bn = blockIdx.x * BN;
    const int warp = tid >> 5, lane = tid & 31;
    const int g    = lane >> 2, t4 = lane & 3;
    const int wm   = (warp & 1) * 64, wn = (warp >> 1) * 32;

    const int a_row = (lane & 7) + 8 * ((lane >> 3) & 1);
    const int a_c8  = (lane >> 4) * 8;
    const int b_row = (lane & 7) + 8 * (lane >> 4);
    const int b_c8  = ((lane >> 3) & 1) * 8;

    const int NC = K / BK;

    auto load_stage = [&](int s, int c) {
        const __half* Aptr = A  + (size_t)bm * K + (size_t)c * BK;
        const __half* Bptr = Bt + (size_t)bn * K + (size_t)c * BK;
        #pragma unroll
        for (int i = 0; i < 4; ++i) {
            int idx = tid + i * 256;
            int row = idx >> 3, c8 = idx & 7;
            uint32_t so = (uint32_t)((s * TILEH + row * LDT + c8 * 8) * 2);
            CP_ASYNC16(as_u + so, Aptr + (size_t)row * K + c8 * 8);
            CP_ASYNC16(bs_u + so, Bptr + (size_t)row * K + c8 * 8);
        }
    };

    float acc[4][4][4];
    #pragma unroll
    for (int mi = 0; mi < 4; ++mi)
        #pragma unroll
        for (int ni = 0; ni < 4; ++ni)
            #pragma unroll
            for (int r = 0; r < 4; ++r) acc[mi][ni][r] = 0.f;

    #pragma unroll
    for (int s = 0; s < STG - 1; ++s) { load_stage(s, s); CP_COMMIT(); }

    for (int c = 0; c < NC; ++c) {
        CP_WAIT(STG - 2);
        __syncthreads();
        if (c + STG - 1 < NC) load_stage((c + STG - 1) % STG, c + STG - 1);
        CP_COMMIT();

        const uint32_t a_base = as_u +
            (uint32_t)(((c % STG) * TILEH + (wm + a_row) * LDT + a_c8) * 2);
        const uint32_t b_base = bs_u +
            (uint32_t)(((c % STG) * TILEH + (wn + b_row) * LDT + b_c8) * 2);

        #pragma unroll
        for (int ks = 0; ks < 4; ++ks) {
            uint32_t af[4][4], bf[4][2];
            #pragma unroll
            for (int mi = 0; mi < 4; ++mi)
                LDSM4(af[mi][0], af[mi][1], af[mi][2], af[mi][3],
                      a_base + (uint32_t)(mi * 16 * LDT * 2 + ks * 32));
            #pragma unroll
            for (int nj = 0; nj < 2; ++nj)
                LDSM4(bf[2 * nj][0], bf[2 * nj][1], bf[2 * nj + 1][0], bf[2 * nj + 1][1],
                      b_base + (uint32_t)(nj * 16 * LDT * 2 + ks * 32));
            #pragma unroll
            for (int mi = 0; mi < 4; ++mi)
                #pragma unroll
                for (int ni = 0; ni < 4; ++ni)
                    mma_f16_16n8k16(acc[mi][ni], af[mi], bf[ni]);
        }
    }

    #pragma unroll
    for (int mi = 0; mi < 4; ++mi) {
        #pragma unroll
        for (int half = 0; half < 2; ++half) {
            int row = bm + wm + mi * 16 + g + half * 8;
            OutT* crow = C + (size_t)row * N;
            const float* rrow = resid ? resid + (size_t)row * N : nullptr;
            #pragma unroll
            for (int ni = 0; ni < 4; ++ni) {
                int col = bn + wn + ni * 8 + 2 * t4;
                float v0 = acc[mi][ni][half * 2 + 0];
                float v1 = acc[mi][ni][half * 2 + 1];
                if (bias) { v0 += bias[col]; v1 += bias[col + 1]; }
                if (rrow) { v0 += rrow[col]; v1 += rrow[col + 1]; }
                if constexpr (sizeof(OutT) == 2) {
                    *(__half2*)&crow[col] = __floats2half2_rn(v0, v1);
                } else {
                    *(float2*)&crow[col] = make_float2(v0, v1);
                }
            }
        }
    }
}

// ---------------------------------------------------------------------------
// Flash attention (R7/R10 proven config, heavy-tile-first ordering).
// ---------------------------------------------------------------------------
#define AT_LQ 136
#define AT_LV 72
#define AT_QS  0
#define AT_KS  (64*AT_LQ)
#define AT_VS  (AT_KS + 2*64*AT_LQ)
#define AT_PS  (AT_VS + 2*128*AT_LV)
#define AT_SMEM_HALVES (AT_PS + 64*AT_LV)
#define AT_SMEM_BYTES  (AT_SMEM_HALVES * 2)     // 98304

__global__ void __launch_bounds__(128) attn_f16_kernel() {
    extern __shared__ __half smh[];
    __half* Qs = smh + AT_QS;   // [64][136]
    __half* Ks = smh + AT_KS;   // [2][64][136]
    __half* Vs = smh + AT_VS;   // [2][128][72]
    __half* Ps = smh + AT_PS;   // [64][72]
    const uint32_t qs_u = smem_u32(Qs), ks_u = smem_u32(Ks), vs_u = smem_u32(Vs);
    const uint32_t ps_u = smem_u32(Ps);

    const int tid = threadIdx.x, warp = tid >> 5, lane = tid & 31;
    const int g = lane >> 2, t4 = lane & 3;
    const int qt = gridDim.x - 1 - blockIdx.x;   // heavy tiles start first
    const int h = blockIdx.y, b = blockIdx.z;
    const int kvh = h >> 2;

    const int a_row = (lane & 7) + 8 * ((lane >> 3) & 1);
    const int a_c8  = (lane >> 4) * 8;
    const int b_row = (lane & 7) + 8 * (lane >> 4);
    const int b_c8  = ((lane >> 3) & 1) * 8;

    {
        const __half* qbase = g_qh + ((size_t)(b * Ss + qt * 64) * NHh + h) * HDd;
        #pragma unroll
        for (int i = 0; i < 8; ++i) {
            int lin = tid + i * 128;
            int r = lin >> 4, c8 = (lin & 15) << 3;
            CP_ASYNC16(qs_u + (uint32_t)((r * AT_LQ + c8) * 2),
                       qbase + (size_t)r * (NHh * HDd) + c8);
        }
    }

    auto load_kv = [&](int st, int kt) {
        const __half* kbase = g_kh + ((size_t)(b * Ss + kt * 64) * KVHh + kvh) * HDd;
        #pragma unroll
        for (int i = 0; i < 8; ++i) {
            int lin = tid + i * 128;
            int r = lin >> 4, c8 = (lin & 15) << 3;
            CP_ASYNC16(ks_u + (uint32_t)((st * 64 * AT_LQ + r * AT_LQ + c8) * 2),
                       kbase + (size_t)r * (KVHh * HDd) + c8);
        }
        const __half* vbase = g_vt + (size_t)(b * KVHh + kvh) * HDd * Ss + kt * 64;
        #pragma unroll
        for (int i = 0; i < 8; ++i) {
            int lin = tid + i * 128;
            int r = lin >> 3, c8 = (lin & 7) << 3;
            CP_ASYNC16(vs_u + (uint32_t)((st * 128 * AT_LV + r * AT_LV + c8) * 2),
                       vbase + (size_t)r * Ss + c8);
        }
    };

    float m_i[2], l_i[2];
    m_i[0] = m_i[1] = -INFINITY;
    l_i[0] = l_i[1] = 0.f;
    float o[16][4];
    #pragma unroll
    for (int ni = 0; ni < 16; ++ni)
        #pragma unroll
        for (int r = 0; r < 4; ++r) o[ni][r] = 0.f;

    load_kv(0, 0); CP_COMMIT();

    const uint32_t qa_base = qs_u +
        (uint32_t)(((16 * warp + a_row) * AT_LQ + a_c8) * 2);
    const uint32_t pa_base = ps_u +
        (uint32_t)(((16 * warp + a_row) * AT_LV + a_c8) * 2);

    for (int kt = 0; kt <= qt; ++kt) {
        const int st = kt & 1;
        CP_WAIT(0);
        __syncthreads();
        if (kt < qt) { load_kv(st ^ 1, kt + 1); CP_COMMIT(); }

        float c[8][4];
        #pragma unroll
        for (int ni = 0; ni < 8; ++ni)
            #pragma unroll
            for (int r = 0; r < 4; ++r) c[ni][r] = 0.f;

        const uint32_t kb_base = ks_u +
            (uint32_t)((st * 64 * AT_LQ + b_row * AT_LQ + b_c8) * 2);
        #pragma unroll
        for (int ks = 0; ks < 8; ++ks) {
            uint32_t af[4], bf[8][2];
            LDSM4(af[0], af[1], af[2], af[3], qa_base + (uint32_t)(ks * 32));
            #pragma unroll
            for (int nj = 0; nj < 4; ++nj)
                LDSM4(bf[2 * nj][0], bf[2 * nj][1], bf[2 * nj + 1][0], bf[2 * nj + 1][1],
                      kb_base + (uint32_t)(nj * 16 * AT_LQ * 2 + ks * 32));
            #pragma unroll
            for (int ni = 0; ni < 8; ++ni)
                mma_f16_16n8k16(c[ni], af, bf[ni]);
        }

        if (kt == qt) {
            #pragma unroll
            for (int r = 0; r < 2; ++r) {
                const int rloc = 16 * warp + g + 8 * r;
                #pragma unroll
                for (int ni = 0; ni < 8; ++ni) {
                    const int cloc = ni * 8 + 2 * t4;
                    if (cloc     > rloc) c[ni][2 * r]     = -INFINITY;
                    if (cloc + 1 > rloc) c[ni][2 * r + 1] = -INFINITY;
                }
            }
        }

        #pragma unroll
        for (int r = 0; r < 2; ++r) {
            float mt = -INFINITY;
            #pragma unroll
            for (int ni = 0; ni < 8; ++ni)
                mt = fmaxf(mt, fmaxf(c[ni][2 * r], c[ni][2 * r + 1]));
            mt = fmaxf(mt, __shfl_xor_sync(0xffffffffu, mt, 1));
            mt = fmaxf(mt, __shfl_xor_sync(0xffffffffu, mt, 2));
            const float mn = fmaxf(m_i[r], mt);
            const float corr = __expf(m_i[r] - mn);
            float rs = 0.f;
            #pragma unroll
            for (int ni = 0; ni < 8; ++ni) {
                float p0 = __expf(c[ni][2 * r]     - mn);
                float p1 = __expf(c[ni][2 * r + 1] - mn);
                rs += p0 + p1;
                *(__half2*)&Ps[(16 * warp + g + 8 * r) * AT_LV + ni * 8 + 2 * t4] =
                    __floats2half2_rn(p0, p1);
            }
            rs += __shfl_xor_sync(0xffffffffu, rs, 1);
            rs += __shfl_xor_sync(0xffffffffu, rs, 2);
            l_i[r] = l_i[r] * corr + rs;
            m_i[r] = mn;
            #pragma unroll
            for (int ni = 0; ni < 16; ++ni) {
                o[ni][2 * r]     *= corr;
                o[ni][2 * r + 1] *= corr;
            }
        }
        __syncwarp();

        const uint32_t vb_base = vs_u +
            (uint32_t)((st * 128 * AT_LV + b_row * AT_LV + b_c8) * 2);
        #pragma unroll
        for (int ks = 0; ks < 4; ++ks) {
            uint32_t af[4], bf[16][2];
            LDSM4(af[0], af[1], af[2], af[3], pa_base + (uint32_t)(ks * 32));
            #pragma unroll
            for (int nj = 0; nj < 8; ++nj)
                LDSM4(bf[2 * nj][0], bf[2 * nj][1], bf[2 * nj + 1][0], bf[2 * nj + 1][1],
                      vb_base + (uint32_t)(nj * 16 * AT_LV * 2 + ks * 32));
            #pragma unroll
            for (int ni = 0; ni < 16; ++ni)
                mma_f16_16n8k16(o[ni], af, bf[ni]);
        }
    }

    #pragma unroll
    for (int r = 0; r < 2; ++r) {
        const float inv = 1.f / l_i[r];
        const int row = qt * 64 + 16 * warp + g + 8 * r;
        __half* obase = g_ctxh + (size_t)(b * Ss + row) * Hh + h * HDd;
        #pragma unroll
        for (int ni = 0; ni < 16; ++ni) {
            const int col = ni * 8 + 2 * t4;
            *(__half2*)&obase[col] = __floats2half2_rn(o[ni][2 * r] * inv,
                                                       o[ni][2 * r + 1] * inv);
        }
    }
}

// ---------------------------------------------------------------------------
extern "C" void kernel_launch(void* const* d_in, const int* in_sizes, int n_in,
                              void* d_out, int out_size) {
    const float* hs  = (const float*)d_in[0];
    const float* res = (const float*)d_in[1];
    const float* Wq  = (const float*)d_in[3];
    const float* Wkv = (const float*)d_in[4];
    const float* Wd  = (const float*)d_in[5];
    const float* bd  = (const float*)d_in[6];
    float* out = (float*)d_out;

    __half *qkvh, *hsh, *wt, *wdt, *ctxh;
    cudaGetSymbolAddress((void**)&qkvh, g_qkvh);
    cudaGetSymbolAddress((void**)&hsh,  g_hsh);
    cudaGetSymbolAddress((void**)&wt,   g_wt);
    cudaGetSymbolAddress((void**)&wdt,  g_wdt);
    cudaGetSymbolAddress((void**)&ctxh, g_ctxh);

    cudaFuncSetAttribute(attn_f16_kernel, cudaFuncAttributeMaxDynamicSharedMemorySize, AT_SMEM_BYTES);
    cudaFuncSetAttribute(gemm_f16_kernel<__half>, cudaFuncAttributeMaxDynamicSharedMemorySize, GSMEM_BYTES);
    cudaFuncSetAttribute(gemm_f16_kernel<float>,  cudaFuncAttributeMaxDynamicSharedMemorySize, GSMEM_BYTES);

    // prep 1: rope table + hs fp16 + all weight transposes (one launch)
    prep1_kernel<<<NB_PREP1, 256>>>(hs, Wq, Wkv, Wd);

    // fused QKV projection: C[4096][6144] fp16
    gemm_f16_kernel<__half><<<dim3(NQKV / BN, Mtot / BM), 256, GSMEM_BYTES>>>(
        hsh, wt, qkvh, NQKV, Hh, nullptr, nullptr);

    // prep 2: RoPE apply + V transpose (one launch)
    prep2_kernel<<<NB_PREP2, 256>>>();

    attn_f16_kernel<<<dim3(Ss / 64, NHh, Bb), 128, AT_SMEM_BYTES>>>();

    gemm_f16_kernel<float><<<dim3(Hh / BN, Mtot / BM), 256, GSMEM_BYTES>>>(
        ctxh, wdt, out, Hh, Hh, bd, res);
}

// round 14
// speedup vs baseline: 1.2436x; 1.0829x over previous
#include <cuda_runtime.h>
#include <cuda_fp16.h>
#include <math.h>
#include <stdint.h>

#define Bb   2
#define Ss   2048
#define Hh   4096
#define NHh  32
#define HDd  128
#define KVHh 8
#define Mtot (Bb*Ss)          // 4096
#define NQKV 6144             // 4096 q + 2048 kv

// ---------------- scratch (allocation-free) ----------------
__device__ float  g_qkv[Mtot*NQKV];           // fused QKV GEMM output (fp32)
__device__ __half g_hsh[Mtot*Hh];             // hs fp16
__device__ __half g_wt[NQKV*Hh];              // [Wq^T ; Wkv^T] fp16 [N][K]
__device__ __half g_wdt[Hh*Hh];               // Wd^T fp16
__device__ __half g_qh[Bb*Ss*NHh*HDd];        // post-RoPE q, pre-scaled, fp16
__device__ __half g_kh[Bb*Ss*KVHh*HDd];       // post-RoPE k, fp16
__device__ __half g_vt[Bb*KVHh*HDd*Ss];       // V transposed [b][kvh][d][s] fp16
__device__ __half g_ctxh[Mtot*Hh];            // attention output fp16
__device__ float  g_cos[Ss*64];
__device__ float  g_sin[Ss*64];

// ---------------- helpers ----------------
__device__ __forceinline__ uint32_t smem_u32(const void* p) {
    uint32_t a;
    asm("{ .reg .u64 t; cvta.to.shared.u64 t, %1; cvt.u32.u64 %0, t; }" : "=r"(a) : "l"(p));
    return a;
}
#define CP_ASYNC16(dst_u32, src_ptr) \
    asm volatile("cp.async.cg.shared.global [%0], [%1], 16;" :: "r"(dst_u32), "l"(src_ptr) : "memory")
#define CP_COMMIT() asm volatile("cp.async.commit_group;" ::: "memory")
#define CP_WAIT(n)  asm volatile("cp.async.wait_group %0;" :: "n"(n) : "memory")

#define LDSM4(r0, r1, r2, r3, addr) \
    asm volatile("ldmatrix.sync.aligned.m8n8.x4.shared.b16 {%0,%1,%2,%3}, [%4];" \
                 : "=r"(r0), "=r"(r1), "=r"(r2), "=r"(r3) : "r"(addr))

__device__ __forceinline__ void mma_f16_16n8k16(float* c, const uint32_t* a, const uint32_t* b) {
    asm volatile(
        "mma.sync.aligned.m16n8k16.row.col.f32.f16.f16.f32 "
        "{%0,%1,%2,%3}, {%4,%5,%6,%7}, {%8,%9}, {%0,%1,%2,%3};"
        : "+f"(c[0]), "+f"(c[1]), "+f"(c[2]), "+f"(c[3])
        : "r"(a[0]), "r"(a[1]), "r"(a[2]), "r"(a[3]), "r"(b[0]), "r"(b[1]));
}

// ---------------------------------------------------------------------------
// prep1: rope tables + hs->fp16 + three weight transposes, one launch.
// 256 threads/block; task decoded from blockIdx.x.
// ---------------------------------------------------------------------------
#define NB_TABLE 512
#define NB_CVT   16384
#define NB_TRQ   16384
#define NB_TRKV  8192
#define NB_TRD   16384
#define NB_PREP1 (NB_TABLE + NB_CVT + NB_TRQ + NB_TRKV + NB_TRD)

__global__ void __launch_bounds__(256) prep1_kernel(
    const float* __restrict__ hs, const float* __restrict__ Wq,
    const float* __restrict__ Wkv, const float* __restrict__ Wd)
{
    __shared__ float t[32][33];
    int blk = blockIdx.x;
    const int tid = threadIdx.x;

    if (blk < NB_TABLE) {                      // rope cos/sin table
        int idx = blk * 256 + tid;
        int s = idx >> 6, j = idx & 63;
        double invf = exp(-(double)j * (log(10000.0) / 64.0));
        float th = (float)s * (float)invf;
        g_cos[idx] = (float)cos((double)th);
        g_sin[idx] = (float)sin((double)th);
        return;
    }
    blk -= NB_TABLE;
    if (blk < NB_CVT) {                        // hs fp32 -> fp16
        int i = blk * 256 + tid;               // float4 index, exactly 4M
        float4 v = ((const float4*)hs)[i];
        __half2* d2 = (__half2*)g_hsh;
        d2[i * 2]     = __floats2half2_rn(v.x, v.y);
        d2[i * 2 + 1] = __floats2half2_rn(v.z, v.w);
        return;
    }
    blk -= NB_CVT;

    // weight transpose tasks: src[K][N] fp32 -> dst[N][K] fp16
    const float* src; __half* dst; int N; int tix;
    if (blk < NB_TRQ)       { src = Wq;  dst = g_wt;                    N = Hh;   tix = blk; }
    else if ((blk -= NB_TRQ) < NB_TRKV) { src = Wkv; dst = g_wt + (size_t)Hh * Hh; N = 2048; tix = blk; }
    else                    { blk -= NB_TRKV; src = Wd; dst = g_wdt;    N = Hh;   tix = blk; }

    const int K = Hh;
    const int ncols = N / 32;
    const int n0 = (tix % ncols) * 32, k0 = (tix / ncols) * 32;
    const int tx = tid & 31, ty = tid >> 5;    // 32 x 8
    #pragma unroll
    for (int i = 0; i < 32; i += 8)
        t[ty + i][tx] = src[(size_t)(k0 + ty + i) * N + n0 + tx];
    __syncthreads();
    #pragma unroll
    for (int i = 0; i < 32; i += 8)
        dst[(size_t)(n0 + ty + i) * K + k0 + tx] = __float2half_rn(t[tx][ty + i]);
}

// ---------------------------------------------------------------------------
// prep2: RoPE apply (q pre-scaled) + V transpose, one launch.
// ---------------------------------------------------------------------------
#define NB_ROPE 40960
#define NB_VT   4096
#define NB_PREP2 (NB_ROPE + NB_VT)

__global__ void __launch_bounds__(256) prep2_kernel() {
    __shared__ float t[32][33];
    int blk = blockIdx.x;
    const int tid = threadIdx.x;

    if (blk < NB_ROPE) {                       // RoPE on q and k
        int idx = blk * 256 + tid;
        const float qscale = 0.08838834764831845f;   // 1/sqrt(128)
        int j    = idx & 63;
        int tt   = idx >> 6;
        int head = tt % (NHh + KVHh);
        int row  = tt / (NHh + KVHh);
        int s    = row & (Ss - 1);
        float c  = g_cos[(s << 6) + j];
        float sn = g_sin[(s << 6) + j];
        if (head < NHh) {
            const float* base = g_qkv + (size_t)row * NQKV + head * HDd;
            float x1 = base[j], x2 = base[j + 64];
            __half* dst = g_qh + ((size_t)row * NHh + head) * HDd;
            dst[j]      = __float2half_rn((x1 * c - x2 * sn) * qscale);
            dst[j + 64] = __float2half_rn((x2 * c + x1 * sn) * qscale);
        } else {
            int kvh = head - NHh;
            const float* base = g_qkv + (size_t)row * NQKV + Hh + kvh * 256;
            float x1 = base[j], x2 = base[j + 64];
            __half* dst = g_kh + ((size_t)row * KVHh + kvh) * HDd;
            dst[j]      = __float2half_rn(x1 * c - x2 * sn);
            dst[j + 64] = __float2half_rn(x2 * c + x1 * sn);
        }
        return;
    }
    blk -= NB_ROPE;                            // V transpose -> g_vt

    int s0 = (blk & 63) * 32;
    int rest = blk >> 6;
    int d0 = (rest & 3) * 32;
    int bk = rest >> 2;                        // b*KVHh + kvh
    int b = bk >> 3, kvh = bk & 7;
    const int tx = tid & 31, ty = tid >> 5;
    const float* src = g_qkv + (size_t)(b * Ss) * NQKV + Hh + kvh * 256 + 128;
    #pragma unroll
    for (int i = 0; i < 32; i += 8)
        t[ty + i][tx] = src[(size_t)(s0 + ty + i) * NQKV + d0 + tx];
    __syncthreads();
    __half* dst = g_vt + (size_t)bk * HDd * Ss;
    #pragma unroll
    for (int i = 0; i < 32; i += 8)
        dst[(size_t)(d0 + ty + i) * Ss + s0 + tx] = __float2half_rn(t[tx][ty + i]);
}

// ---------------------------------------------------------------------------
// fp16 mma.sync GEMM (proven config): CTA 128x128, 8 warps 64x32, BK=64,
// 3-stage cp.async, ldmatrix. 110.6KB smem -> 2 CTAs/SM.
// ---------------------------------------------------------------------------
#define BM 128
#define BN 128
#define BK 64
#define STG 3
#define LDT 72
#define TILEH (BM * LDT)                  // halves per tile per stage
#define GSMEM_BYTES (STG * 2 * TILEH * 2) // 110592

__global__ void __launch_bounds__(256) gemm_f16_kernel(
    const __half* __restrict__ A, const __half* __restrict__ Bt,
    float* __restrict__ C, int N, int K,
    const float* __restrict__ bias, const float* __restrict__ resid)
{
    extern __shared__ __half smh[];
    __half* As = smh;                 // [STG][BM][LDT]
    __half* Bs = smh + STG * TILEH;   // [STG][BN][LDT]
    const uint32_t as_u = smem_u32(As);
    const uint32_t bs_u = smem_u32(Bs);

    const int tid  = threadIdx.x;
    const int bm   = blockIdx.y * BM, bn = blockIdx.x * BN;
    const int warp = tid >> 5, lane = tid & 31;
    const int g    = lane >> 2, t4 = lane & 3;
    const int wm   = (warp & 1) * 64, wn = (warp >> 1) * 32;

    const int a_row = (lane & 7) + 8 * ((lane >> 3) & 1);
    const int a_c8  = (lane >> 4) * 8;
    const int b_row = (lane & 7) + 8 * (lane >> 4);
    const int b_c8  = ((lane >> 3) & 1) * 8;

    const int NC = K / BK;

    auto load_stage = [&](int s, int c) {
        const __half* Aptr = A  + (size_t)bm * K + (size_t)c * BK;
        const __half* Bptr = Bt + (size_t)bn * K + (size_t)c * BK;
        #pragma unroll
        for (int i = 0; i < 4; ++i) {
            int idx = tid + i * 256;
            int row = idx >> 3, c8 = idx & 7;
            uint32_t so = (uint32_t)((s * TILEH + row * LDT + c8 * 8) * 2);
            CP_ASYNC16(as_u + so, Aptr + (size_t)row * K + c8 * 8);
            CP_ASYNC16(bs_u + so, Bptr + (size_t)row * K + c8 * 8);
        }
    };

    float acc[4][4][4];
    #pragma unroll
    for (int mi = 0; mi < 4; ++mi)
        #pragma unroll
        for (int ni = 0; ni < 4; ++ni)
            #pragma unroll
            for (int r = 0; r < 4; ++r) acc[mi][ni][r] = 0.f;

    #pragma unroll
    for (int s = 0; s < STG - 1; ++s) { load_stage(s, s); CP_COMMIT(); }

    for (int c = 0; c < NC; ++c) {
        CP_WAIT(STG - 2);
        __syncthreads();
        if (c + STG - 1 < NC) load_stage((c + STG - 1) % STG, c + STG - 1);
        CP_COMMIT();

        const uint32_t a_base = as_u +
            (uint32_t)(((c % STG) * TILEH + (wm + a_row) * LDT + a_c8) * 2);
        const uint32_t b_base = bs_u +
            (uint32_t)(((c % STG) * TILEH + (wn + b_row) * LDT + b_c8) * 2);

        #pragma unroll
        for (int ks = 0; ks < 4; ++ks) {
            uint32_t af[4][4], bf[4][2];
            #pragma unroll
            for (int mi = 0; mi < 4; ++mi)
                LDSM4(af[mi][0], af[mi][1], af[mi][2], af[mi][3],
                      a_base + (uint32_t)(mi * 16 * LDT * 2 + ks * 32));
            #pragma unroll
            for (int nj = 0; nj < 2; ++nj)
                LDSM4(bf[2 * nj][0], bf[2 * nj][1], bf[2 * nj + 1][0], bf[2 * nj + 1][1],
                      b_base + (uint32_t)(nj * 16 * LDT * 2 + ks * 32));
            #pragma unroll
            for (int mi = 0; mi < 4; ++mi)
                #pragma unroll
                for (int ni = 0; ni < 4; ++ni)
                    mma_f16_16n8k16(acc[mi][ni], af[mi], bf[ni]);
        }
    }

    #pragma unroll
    for (int mi = 0; mi < 4; ++mi) {
        #pragma unroll
        for (int half = 0; half < 2; ++half) {
            int row = bm + wm + mi * 16 + g + half * 8;
            float* crow = C + (size_t)row * N;
            const float* rrow = resid ? resid + (size_t)row * N : nullptr;
            #pragma unroll
            for (int ni = 0; ni < 4; ++ni) {
                int col = bn + wn + ni * 8 + 2 * t4;
                float v0 = acc[mi][ni][half * 2 + 0];
                float v1 = acc[mi][ni][half * 2 + 1];
                if (bias) { v0 += bias[col]; v1 += bias[col + 1]; }
                if (rrow) { v0 += rrow[col]; v1 += rrow[col + 1]; }
                *(float2*)&crow[col] = make_float2(v0, v1);
            }
        }
    }
}

// ---------------------------------------------------------------------------
// Flash attention (proven config, heavy-tile-first ordering).
// CTA = (64-row Q tile, head, batch); 128 threads / 4 warps, 16 Q rows/warp.
// ---------------------------------------------------------------------------
#define AT_LQ 136
#define AT_LV 72
#define AT_QS  0
#define AT_KS  (64*AT_LQ)                       // 8704
#define AT_VS  (AT_KS + 2*64*AT_LQ)             // + 17408
#define AT_PS  (AT_VS + 2*128*AT_LV)            // + 18432
#define AT_SMEM_HALVES (AT_PS + 64*AT_LV)
#define AT_SMEM_BYTES  (AT_SMEM_HALVES * 2)     // 98304

__global__ void __launch_bounds__(128) attn_f16_kernel() {
    extern __shared__ __half smh[];
    __half* Qs = smh + AT_QS;   // [64][136]
    __half* Ks = smh + AT_KS;   // [2][64][136]
    __half* Vs = smh + AT_VS;   // [2][128][72]
    __half* Ps = smh + AT_PS;   // [64][72]
    const uint32_t qs_u = smem_u32(Qs), ks_u = smem_u32(Ks), vs_u = smem_u32(Vs);
    const uint32_t ps_u = smem_u32(Ps);

    const int tid = threadIdx.x, warp = tid >> 5, lane = tid & 31;
    const int g = lane >> 2, t4 = lane & 3;
    const int qt = gridDim.x - 1 - blockIdx.x;   // heavy tiles start first
    const int h = blockIdx.y, b = blockIdx.z;
    const int kvh = h >> 2;

    const int a_row = (lane & 7) + 8 * ((lane >> 3) & 1);
    const int a_c8  = (lane >> 4) * 8;
    const int b_row = (lane & 7) + 8 * (lane >> 4);
    const int b_c8  = ((lane >> 3) & 1) * 8;

    // Q tile (pre-scaled fp16): 64 rows x 128 halves via cp.async
    {
        const __half* qbase = g_qh + ((size_t)(b * Ss + qt * 64) * NHh + h) * HDd;
        #pragma unroll
        for (int i = 0; i < 8; ++i) {
            int lin = tid + i * 128;
            int r = lin >> 4, c8 = (lin & 15) << 3;
            CP_ASYNC16(qs_u + (uint32_t)((r * AT_LQ + c8) * 2),
                       qbase + (size_t)r * (NHh * HDd) + c8);
        }
    }

    auto load_kv = [&](int st, int kt) {
        const __half* kbase = g_kh + ((size_t)(b * Ss + kt * 64) * KVHh + kvh) * HDd;
        #pragma unroll
        for (int i = 0; i < 8; ++i) {
            int lin = tid + i * 128;
            int r = lin >> 4, c8 = (lin & 15) << 3;
            CP_ASYNC16(ks_u + (uint32_t)((st * 64 * AT_LQ + r * AT_LQ + c8) * 2),
                       kbase + (size_t)r * (KVHh * HDd) + c8);
        }
        const __half* vbase = g_vt + (size_t)(b * KVHh + kvh) * HDd * Ss + kt * 64;
        #pragma unroll
        for (int i = 0; i < 8; ++i) {
            int lin = tid + i * 128;
            int r = lin >> 3, c8 = (lin & 7) << 3;
            CP_ASYNC16(vs_u + (uint32_t)((st * 128 * AT_LV + r * AT_LV + c8) * 2),
                       vbase + (size_t)r * Ss + c8);
        }
    };

    float m_i[2], l_i[2];
    m_i[0] = m_i[1] = -INFINITY;
    l_i[0] = l_i[1] = 0.f;
    float o[16][4];
    #pragma unroll
    for (int ni = 0; ni < 16; ++ni)
        #pragma unroll
        for (int r = 0; r < 4; ++r) o[ni][r] = 0.f;

    load_kv(0, 0); CP_COMMIT();

    const uint32_t qa_base = qs_u +
        (uint32_t)(((16 * warp + a_row) * AT_LQ + a_c8) * 2);
    const uint32_t pa_base = ps_u +
        (uint32_t)(((16 * warp + a_row) * AT_LV + a_c8) * 2);

    for (int kt = 0; kt <= qt; ++kt) {
        const int st = kt & 1;
        CP_WAIT(0);
        __syncthreads();
        if (kt < qt) { load_kv(st ^ 1, kt + 1); CP_COMMIT(); }

        // ---- S = Q K^T : 8 n-tiles x 8 k-steps ----
        float c[8][4];
        #pragma unroll
        for (int ni = 0; ni < 8; ++ni)
            #pragma unroll
            for (int r = 0; r < 4; ++r) c[ni][r] = 0.f;

        const uint32_t kb_base = ks_u +
            (uint32_t)((st * 64 * AT_LQ + b_row * AT_LQ + b_c8) * 2);
        #pragma unroll
        for (int ks = 0; ks < 8; ++ks) {
            uint32_t af[4], bf[8][2];
            LDSM4(af[0], af[1], af[2], af[3], qa_base + (uint32_t)(ks * 32));
            #pragma unroll
            for (int nj = 0; nj < 4; ++nj)
                LDSM4(bf[2 * nj][0], bf[2 * nj][1], bf[2 * nj + 1][0], bf[2 * nj + 1][1],
                      kb_base + (uint32_t)(nj * 16 * AT_LQ * 2 + ks * 32));
            #pragma unroll
            for (int ni = 0; ni < 8; ++ni)
                mma_f16_16n8k16(c[ni], af, bf[ni]);
        }

        if (kt == qt) {   // causal mask on diagonal tile
            #pragma unroll
            for (int r = 0; r < 2; ++r) {
                const int rloc = 16 * warp + g + 8 * r;
                #pragma unroll
                for (int ni = 0; ni < 8; ++ni) {
                    const int cloc = ni * 8 + 2 * t4;
                    if (cloc     > rloc) c[ni][2 * r]     = -INFINITY;
                    if (cloc + 1 > rloc) c[ni][2 * r + 1] = -INFINITY;
                }
            }
        }

        // ---- online softmax (fp32, in-register + quad shuffle) ----
        #pragma unroll
        for (int r = 0; r < 2; ++r) {
            float mt = -INFINITY;
            #pragma unroll
            for (int ni = 0; ni < 8; ++ni)
                mt = fmaxf(mt, fmaxf(c[ni][2 * r], c[ni][2 * r + 1]));
            mt = fmaxf(mt, __shfl_xor_sync(0xffffffffu, mt, 1));
            mt = fmaxf(mt, __shfl_xor_sync(0xffffffffu, mt, 2));
            const float mn = fmaxf(m_i[r], mt);
            const float corr = __expf(m_i[r] - mn);
            float rs = 0.f;
            #pragma unroll
            for (int ni = 0; ni < 8; ++ni) {
                float p0 = __expf(c[ni][2 * r]     - mn);
                float p1 = __expf(c[ni][2 * r + 1] - mn);
                rs += p0 + p1;
                *(__half2*)&Ps[(16 * warp + g + 8 * r) * AT_LV + ni * 8 + 2 * t4] =
                    __floats2half2_rn(p0, p1);
            }
            rs += __shfl_xor_sync(0xffffffffu, rs, 1);
            rs += __shfl_xor_sync(0xffffffffu, rs, 2);
            l_i[r] = l_i[r] * corr + rs;
            m_i[r] = mn;
            #pragma unroll
            for (int ni = 0; ni < 16; ++ni) {
                o[ni][2 * r]     *= corr;
                o[ni][2 * r + 1] *= corr;
            }
        }
        __syncwarp();   // P rows are warp-private: order stores before ldmatrix

        // ---- O += P V : 16 n-tiles x 4 k-steps ----
        const uint32_t vb_base = vs_u +
            (uint32_t)((st * 128 * AT_LV + b_row * AT_LV + b_c8) * 2);
        #pragma unroll
        for (int ks = 0; ks < 4; ++ks) {
            uint32_t af[4], bf[16][2];
            LDSM4(af[0], af[1], af[2], af[3], pa_base + (uint32_t)(ks * 32));
            #pragma unroll
            for (int nj = 0; nj < 8; ++nj)
                LDSM4(bf[2 * nj][0], bf[2 * nj][1], bf[2 * nj + 1][0], bf[2 * nj + 1][1],
                      vb_base + (uint32_t)(nj * 16 * AT_LV * 2 + ks * 32));
            #pragma unroll
            for (int ni = 0; ni < 16; ++ni)
                mma_f16_16n8k16(o[ni], af, bf[ni]);
        }
    }

    // ---- normalize + store ctx (fp16) ----
    #pragma unroll
    for (int r = 0; r < 2; ++r) {
        const float inv = 1.f / l_i[r];
        const int row = qt * 64 + 16 * warp + g + 8 * r;
        __half* obase = g_ctxh + (size_t)(b * Ss + row) * Hh + h * HDd;
        #pragma unroll
        for (int ni = 0; ni < 16; ++ni) {
            const int col = ni * 8 + 2 * t4;
            *(__half2*)&obase[col] = __floats2half2_rn(o[ni][2 * r] * inv,
                                                       o[ni][2 * r + 1] * inv);
        }
    }
}

// ---------------------------------------------------------------------------
extern "C" void kernel_launch(void* const* d_in, const int* in_sizes, int n_in,
                              void* d_out, int out_size) {
    const float* hs  = (const float*)d_in[0];
    const float* res = (const float*)d_in[1];
    const float* Wq  = (const float*)d_in[3];
    const float* Wkv = (const float*)d_in[4];
    const float* Wd  = (const float*)d_in[5];
    const float* bd  = (const float*)d_in[6];
    float* out = (float*)d_out;

    float* qkvp;
    __half *hsh, *wt, *wdt, *ctxh;
    cudaGetSymbolAddress((void**)&qkvp, g_qkv);
    cudaGetSymbolAddress((void**)&hsh,  g_hsh);
    cudaGetSymbolAddress((void**)&wt,   g_wt);
    cudaGetSymbolAddress((void**)&wdt,  g_wdt);
    cudaGetSymbolAddress((void**)&ctxh, g_ctxh);

    cudaFuncSetAttribute(attn_f16_kernel, cudaFuncAttributeMaxDynamicSharedMemorySize, AT_SMEM_BYTES);
    cudaFuncSetAttribute(gemm_f16_kernel, cudaFuncAttributeMaxDynamicSharedMemorySize, GSMEM_BYTES);

    // prep 1: rope table + hs fp16 + all weight transposes (one launch)
    prep1_kernel<<<NB_PREP1, 256>>>(hs, Wq, Wkv, Wd);

    // fused QKV projection: C[4096][6144]
    gemm_f16_kernel<<<dim3(NQKV / BN, Mtot / BM), 256, GSMEM_BYTES>>>(
        hsh, wt, qkvp, NQKV, Hh, nullptr, nullptr);

    // prep 2: RoPE apply + V transpose (one launch)
    prep2_kernel<<<NB_PREP2, 256>>>();

    attn_f16_kernel<<<dim3(Ss / 64, NHh, Bb), 128, AT_SMEM_BYTES>>>();

    gemm_f16_kernel<<<dim3(Hh / BN, Mtot / BM), 256, GSMEM_BYTES>>>(
        ctxh, wdt, out, Hh, Hh, bd, res);
}

// round 17
// speedup vs baseline: 1.2570x; 1.0107x over previous
#include <cuda_runtime.h>
#include <cuda_fp16.h>
#include <math.h>
#include <stdint.h>

#define Bb   2
#define Ss   2048
#define Hh   4096
#define NHh  32
#define HDd  128
#define KVHh 8
#define Mtot (Bb*Ss)          // 4096
#define NQKV 6144             // 4096 q + 2048 kv

// ---------------- scratch (allocation-free) ----------------
__device__ float  g_qkv[Mtot*NQKV];           // fused QKV GEMM output (fp32)
__device__ __half g_hsh[Mtot*Hh];             // hs fp16
__device__ __half g_wt[NQKV*Hh];              // [Wq^T ; Wkv^T] fp16 [N][K]
__device__ __half g_wdt[Hh*Hh];               // Wd^T fp16
__device__ __half g_qh[Bb*Ss*NHh*HDd];        // post-RoPE q, pre-scaled, fp16
__device__ __half g_kh[Bb*Ss*KVHh*HDd];       // post-RoPE k, fp16
__device__ __half g_vt[Bb*KVHh*HDd*Ss];       // V transposed [b][kvh][d][s] fp16
__device__ __half g_ctxh[Mtot*Hh];            // attention output fp16
__device__ float  g_cos[Ss*64];
__device__ float  g_sin[Ss*64];

// ---------------- helpers ----------------
__device__ __forceinline__ uint32_t smem_u32(const void* p) {
    uint32_t a;
    asm("{ .reg .u64 t; cvta.to.shared.u64 t, %1; cvt.u32.u64 %0, t; }" : "=r"(a) : "l"(p));
    return a;
}
#define CP_ASYNC16(dst_u32, src_ptr) \
    asm volatile("cp.async.cg.shared.global [%0], [%1], 16;" :: "r"(dst_u32), "l"(src_ptr) : "memory")
#define CP_COMMIT() asm volatile("cp.async.commit_group;" ::: "memory")
#define CP_WAIT(n)  asm volatile("cp.async.wait_group %0;" :: "n"(n) : "memory")

#define LDSM4(r0, r1, r2, r3, addr) \
    asm volatile("ldmatrix.sync.aligned.m8n8.x4.shared.b16 {%0,%1,%2,%3}, [%4];" \
                 : "=r"(r0), "=r"(r1), "=r"(r2), "=r"(r3) : "r"(addr))

__device__ __forceinline__ void mma_f16_16n8k16(float* c, const uint32_t* a, const uint32_t* b) {
    asm volatile(
        "mma.sync.aligned.m16n8k16.row.col.f32.f16.f16.f32 "
        "{%0,%1,%2,%3}, {%4,%5,%6,%7}, {%8,%9}, {%0,%1,%2,%3};"
        : "+f"(c[0]), "+f"(c[1]), "+f"(c[2]), "+f"(c[3])
        : "r"(a[0]), "r"(a[1]), "r"(a[2]), "r"(a[3]), "r"(b[0]), "r"(b[1]));
}

// ---------------------------------------------------------------------------
// prep1: rope tables + hs->fp16 + Wq/Wkv transposes (Wd moved to side stream).
// ---------------------------------------------------------------------------
#define NB_TABLE 512
#define NB_CVT   16384
#define NB_TRQ   16384
#define NB_TRKV  8192
#define NB_PREP1 (NB_TABLE + NB_CVT + NB_TRQ + NB_TRKV)

__global__ void __launch_bounds__(256) prep1_kernel(
    const float* __restrict__ hs, const float* __restrict__ Wq,
    const float* __restrict__ Wkv)
{
    __shared__ float t[32][33];
    int blk = blockIdx.x;
    const int tid = threadIdx.x;

    if (blk < NB_TABLE) {                      // rope cos/sin table
        int idx = blk * 256 + tid;
        int s = idx >> 6, j = idx & 63;
        double invf = exp(-(double)j * (log(10000.0) / 64.0));
        float th = (float)s * (float)invf;
        g_cos[idx] = (float)cos((double)th);
        g_sin[idx] = (float)sin((double)th);
        return;
    }
    blk -= NB_TABLE;
    if (blk < NB_CVT) {                        // hs fp32 -> fp16
        int i = blk * 256 + tid;
        float4 v = ((const float4*)hs)[i];
        __half2* d2 = (__half2*)g_hsh;
        d2[i * 2]     = __floats2half2_rn(v.x, v.y);
        d2[i * 2 + 1] = __floats2half2_rn(v.z, v.w);
        return;
    }
    blk -= NB_CVT;

    const float* src; __half* dst; int N; int tix;
    if (blk < NB_TRQ) { src = Wq;  dst = g_wt;                     N = Hh;   tix = blk; }
    else              { blk -= NB_TRQ; src = Wkv; dst = g_wt + (size_t)Hh * Hh; N = 2048; tix = blk; }

    const int K = Hh;
    const int ncols = N / 32;
    const int n0 = (tix % ncols) * 32, k0 = (tix / ncols) * 32;
    const int tx = tid & 31, ty = tid >> 5;
    #pragma unroll
    for (int i = 0; i < 32; i += 8)
        t[ty + i][tx] = src[(size_t)(k0 + ty + i) * N + n0 + tx];
    __syncthreads();
    #pragma unroll
    for (int i = 0; i < 32; i += 8)
        dst[(size_t)(n0 + ty + i) * K + k0 + tx] = __float2half_rn(t[tx][ty + i]);
}

// Wd transpose: src[K][N]=Wd fp32 -> g_wdt[N][K] fp16 (runs on side stream)
__global__ void __launch_bounds__(256) wdtrans_kernel(const float* __restrict__ Wd) {
    __shared__ float t[32][33];
    const int tid = threadIdx.x;
    const int N = Hh, K = Hh;
    const int ncols = N / 32;
    const int n0 = (blockIdx.x % ncols) * 32, k0 = (blockIdx.x / ncols) * 32;
    const int tx = tid & 31, ty = tid >> 5;
    #pragma unroll
    for (int i = 0; i < 32; i += 8)
        t[ty + i][tx] = Wd[(size_t)(k0 + ty + i) * N + n0 + tx];
    __syncthreads();
    #pragma unroll
    for (int i = 0; i < 32; i += 8)
        g_wdt[(size_t)(n0 + ty + i) * K + k0 + tx] = __float2half_rn(t[tx][ty + i]);
}

// ---------------------------------------------------------------------------
// prep2q: RoPE on q only (pre-scaled). Depends only on the Q columns of g_qkv.
// ---------------------------------------------------------------------------
#define NB_ROPEQ 32768   // Bb*Ss*NHh*64 / 256

__global__ void __launch_bounds__(256) prep2q_kernel() {
    int idx = blockIdx.x * 256 + threadIdx.x;
    const float qscale = 0.08838834764831845f;   // 1/sqrt(128)
    int j    = idx & 63;
    int tt   = idx >> 6;
    int head = tt % NHh;
    int row  = tt / NHh;
    int s    = row & (Ss - 1);
    float c  = g_cos[(s << 6) + j];
    float sn = g_sin[(s << 6) + j];
    const float* base = g_qkv + (size_t)row * NQKV + head * HDd;
    float x1 = base[j], x2 = base[j + 64];
    __half* dst = g_qh + ((size_t)row * NHh + head) * HDd;
    dst[j]      = __float2half_rn((x1 * c - x2 * sn) * qscale);
    dst[j + 64] = __float2half_rn((x2 * c + x1 * sn) * qscale);
}

// ---------------------------------------------------------------------------
// prep2kv: RoPE on k + V transpose. Depends on the KV columns of g_qkv.
// ---------------------------------------------------------------------------
#define NB_ROPEK 8192    // Bb*Ss*KVHh*64 / 256
#define NB_VT    4096
#define NB_PREP2KV (NB_ROPEK + NB_VT)

__global__ void __launch_bounds__(256) prep2kv_kernel() {
    __shared__ float t[32][33];
    int blk = blockIdx.x;
    const int tid = threadIdx.x;

    if (blk < NB_ROPEK) {                      // RoPE on k
        int idx = blk * 256 + tid;
        int j    = idx & 63;
        int tt   = idx >> 6;
        int kvh  = tt % KVHh;
        int row  = tt / KVHh;
        int s    = row & (Ss - 1);
        float c  = g_cos[(s << 6) + j];
        float sn = g_sin[(s << 6) + j];
        const float* base = g_qkv + (size_t)row * NQKV + Hh + kvh * 256;
        float x1 = base[j], x2 = base[j + 64];
        __half* dst = g_kh + ((size_t)row * KVHh + kvh) * HDd;
        dst[j]      = __float2half_rn(x1 * c - x2 * sn);
        dst[j + 64] = __float2half_rn(x2 * c + x1 * sn);
        return;
    }
    blk -= NB_ROPEK;                           // V transpose -> g_vt

    int s0 = (blk & 63) * 32;
    int rest = blk >> 6;
    int d0 = (rest & 3) * 32;
    int bk = rest >> 2;                        // b*KVHh + kvh
    int b = bk >> 3, kvh = bk & 7;
    const int tx = tid & 31, ty = tid >> 5;
    const float* src = g_qkv + (size_t)(b * Ss) * NQKV + Hh + kvh * 256 + 128;
    #pragma unroll
    for (int i = 0; i < 32; i += 8)
        t[ty + i][tx] = src[(size_t)(s0 + ty + i) * NQKV + d0 + tx];
    __syncthreads();
    __half* dst = g_vt + (size_t)bk * HDd * Ss;
    #pragma unroll
    for (int i = 0; i < 32; i += 8)
        dst[(size_t)(d0 + ty + i) * Ss + s0 + tx] = __float2half_rn(t[tx][ty + i]);
}

// ---------------------------------------------------------------------------
// fp16 mma.sync GEMM (proven config): CTA 128x128, 8 warps 64x32, BK=64,
// 3-stage cp.async, ldmatrix. 110.6KB smem -> 2 CTAs/SM. N = row stride of C.
// ---------------------------------------------------------------------------
#define BM 128
#define BN 128
#define BK 64
#define STG 3
#define LDT 72
#define TILEH (BM * LDT)                  // halves per tile per stage
#define GSMEM_BYTES (STG * 2 * TILEH * 2) // 110592

__global__ void __launch_bounds__(256) gemm_f16_kernel(
    const __half* __restrict__ A, const __half* __restrict__ Bt,
    float* __restrict__ C, int N, int K,
    const float* __restrict__ bias, const float* __restrict__ resid)
{
    extern __shared__ __half smh[];
    __half* As = smh;                 // [STG][BM][LDT]
    __half* Bs = smh + STG * TILEH;   // [STG][BN][LDT]
    const uint32_t as_u = smem_u32(As);
    const uint32_t bs_u = smem_u32(Bs);

    const int tid  = threadIdx.x;
    const int bm   = blockIdx.y * BM, bn = blockIdx.x * BN;
    const int warp = tid >> 5, lane = tid & 31;
    const int g    = lane >> 2, t4 = lane & 3;
    const int wm   = (warp & 1) * 64, wn = (warp >> 1) * 32;

    const int a_row = (lane & 7) + 8 * ((lane >> 3) & 1);
    const int a_c8  = (lane >> 4) * 8;
    const int b_row = (lane & 7) + 8 * (lane >> 4);
    const int b_c8  = ((lane >> 3) & 1) * 8;

    const int NC = K / BK;

    auto load_stage = [&](int s, int c) {
        const __half* Aptr = A  + (size_t)bm * K + (size_t)c * BK;
        const __half* Bptr = Bt + (size_t)bn * K + (size_t)c * BK;
        #pragma unroll
        for (int i = 0; i < 4; ++i) {
            int idx = tid + i * 256;
            int row = idx >> 3, c8 = idx & 7;
            uint32_t so = (uint32_t)((s * TILEH + row * LDT + c8 * 8) * 2);
            CP_ASYNC16(as_u + so, Aptr + (size_t)row * K + c8 * 8);
            CP_ASYNC16(bs_u + so, Bptr + (size_t)row * K + c8 * 8);
        }
    };

    float acc[4][4][4];
    #pragma unroll
    for (int mi = 0; mi < 4; ++mi)
        #pragma unroll
        for (int ni = 0; ni < 4; ++ni)
            #pragma unroll
            for (int r = 0; r < 4; ++r) acc[mi][ni][r] = 0.f;

    #pragma unroll
    for (int s = 0; s < STG - 1; ++s) { load_stage(s, s); CP_COMMIT(); }

    for (int c = 0; c < NC; ++c) {
        CP_WAIT(STG - 2);
        __syncthreads();
        if (c + STG - 1 < NC) load_stage((c + STG - 1) % STG, c + STG - 1);
        CP_COMMIT();

        const uint32_t a_base = as_u +
            (uint32_t)(((c % STG) * TILEH + (wm + a_row) * LDT + a_c8) * 2);
        const uint32_t b_base = bs_u +
            (uint32_t)(((c % STG) * TILEH + (wn + b_row) * LDT + b_c8) * 2);

        #pragma unroll
        for (int ks = 0; ks < 4; ++ks) {
            uint32_t af[4][4], bf[4][2];
            #pragma unroll
            for (int mi = 0; mi < 4; ++mi)
                LDSM4(af[mi][0], af[mi][1], af[mi][2], af[mi][3],
                      a_base + (uint32_t)(mi * 16 * LDT * 2 + ks * 32));
            #pragma unroll
            for (int nj = 0; nj < 2; ++nj)
                LDSM4(bf[2 * nj][0], bf[2 * nj][1], bf[2 * nj + 1][0], bf[2 * nj + 1][1],
                      b_base + (uint32_t)(nj * 16 * LDT * 2 + ks * 32));
            #pragma unroll
            for (int mi = 0; mi < 4; ++mi)
                #pragma unroll
                for (int ni = 0; ni < 4; ++ni)
                    mma_f16_16n8k16(acc[mi][ni], af[mi], bf[ni]);
        }
    }

    #pragma unroll
    for (int mi = 0; mi < 4; ++mi) {
        #pragma unroll
        for (int half = 0; half < 2; ++half) {
            int row = bm + wm + mi * 16 + g + half * 8;
            float* crow = C + (size_t)row * N;
            const float* rrow = resid ? resid + (size_t)row * N : nullptr;
            #pragma unroll
            for (int ni = 0; ni < 4; ++ni) {
                int col = bn + wn + ni * 8 + 2 * t4;
                float v0 = acc[mi][ni][half * 2 + 0];
                float v1 = acc[mi][ni][half * 2 + 1];
                if (bias) { v0 += bias[col]; v1 += bias[col + 1]; }
                if (rrow) { v0 += rrow[col]; v1 += rrow[col + 1]; }
                *(float2*)&crow[col] = make_float2(v0, v1);
            }
        }
    }
}

// ---------------------------------------------------------------------------
// Flash attention (proven config, heavy-tile-first ordering).
// ---------------------------------------------------------------------------
#define AT_LQ 136
#define AT_LV 72
#define AT_QS  0
#define AT_KS  (64*AT_LQ)
#define AT_VS  (AT_KS + 2*64*AT_LQ)
#define AT_PS  (AT_VS + 2*128*AT_LV)
#define AT_SMEM_HALVES (AT_PS + 64*AT_LV)
#define AT_SMEM_BYTES  (AT_SMEM_HALVES * 2)     // 98304

__global__ void __launch_bounds__(128) attn_f16_kernel() {
    extern __shared__ __half smh[];
    __half* Qs = smh + AT_QS;   // [64][136]
    __half* Ks = smh + AT_KS;   // [2][64][136]
    __half* Vs = smh + AT_VS;   // [2][128][72]
    __half* Ps = smh + AT_PS;   // [64][72]
    const uint32_t qs_u = smem_u32(Qs), ks_u = smem_u32(Ks), vs_u = smem_u32(Vs);
    const uint32_t ps_u = smem_u32(Ps);

    const int tid = threadIdx.x, warp = tid >> 5, lane = tid & 31;
    const int g = lane >> 2, t4 = lane & 3;
    const int qt = gridDim.x - 1 - blockIdx.x;   // heavy tiles start first
    const int h = blockIdx.y, b = blockIdx.z;
    const int kvh = h >> 2;

    const int a_row = (lane & 7) + 8 * ((lane >> 3) & 1);
    const int a_c8  = (lane >> 4) * 8;
    const int b_row = (lane & 7) + 8 * (lane >> 4);
    const int b_c8  = ((lane >> 3) & 1) * 8;

    {
        const __half* qbase = g_qh + ((size_t)(b * Ss + qt * 64) * NHh + h) * HDd;
        #pragma unroll
        for (int i = 0; i < 8; ++i) {
            int lin = tid + i * 128;
            int r = lin >> 4, c8 = (lin & 15) << 3;
            CP_ASYNC16(qs_u + (uint32_t)((r * AT_LQ + c8) * 2),
                       qbase + (size_t)r * (NHh * HDd) + c8);
        }
    }

    auto load_kv = [&](int st, int kt) {
        const __half* kbase = g_kh + ((size_t)(b * Ss + kt * 64) * KVHh + kvh) * HDd;
        #pragma unroll
        for (int i = 0; i < 8; ++i) {
            int lin = tid + i * 128;
            int r = lin >> 4, c8 = (lin & 15) << 3;
            CP_ASYNC16(ks_u + (uint32_t)((st * 64 * AT_LQ + r * AT_LQ + c8) * 2),
                       kbase + (size_t)r * (KVHh * HDd) + c8);
        }
        const __half* vbase = g_vt + (size_t)(b * KVHh + kvh) * HDd * Ss + kt * 64;
        #pragma unroll
        for (int i = 0; i < 8; ++i) {
            int lin = tid + i * 128;
            int r = lin >> 3, c8 = (lin & 7) << 3;
            CP_ASYNC16(vs_u + (uint32_t)((st * 128 * AT_LV + r * AT_LV + c8) * 2),
                       vbase + (size_t)r * Ss + c8);
        }
    };

    float m_i[2], l_i[2];
    m_i[0] = m_i[1] = -INFINITY;
    l_i[0] = l_i[1] = 0.f;
    float o[16][4];
    #pragma unroll
    for (int ni = 0; ni < 16; ++ni)
        #pragma unroll
        for (int r = 0; r < 4; ++r) o[ni][r] = 0.f;

    load_kv(0, 0); CP_COMMIT();

    const uint32_t qa_base = qs_u +
        (uint32_t)(((16 * warp + a_row) * AT_LQ + a_c8) * 2);
    const uint32_t pa_base = ps_u +
        (uint32_t)(((16 * warp + a_row) * AT_LV + a_c8) * 2);

    for (int kt = 0; kt <= qt; ++kt) {
        const int st = kt & 1;
        CP_WAIT(0);
        __syncthreads();
        if (kt < qt) { load_kv(st ^ 1, kt + 1); CP_COMMIT(); }

        float c[8][4];
        #pragma unroll
        for (int ni = 0; ni < 8; ++ni)
            #pragma unroll
            for (int r = 0; r < 4; ++r) c[ni][r] = 0.f;

        const uint32_t kb_base = ks_u +
            (uint32_t)((st * 64 * AT_LQ + b_row * AT_LQ + b_c8) * 2);
        #pragma unroll
        for (int ks = 0; ks < 8; ++ks) {
            uint32_t af[4], bf[8][2];
            LDSM4(af[0], af[1], af[2], af[3], qa_base + (uint32_t)(ks * 32));
            #pragma unroll
            for (int nj = 0; nj < 4; ++nj)
                LDSM4(bf[2 * nj][0], bf[2 * nj][1], bf[2 * nj + 1][0], bf[2 * nj + 1][1],
                      kb_base + (uint32_t)(nj * 16 * AT_LQ * 2 + ks * 32));
            #pragma unroll
            for (int ni = 0; ni < 8; ++ni)
                mma_f16_16n8k16(c[ni], af, bf[ni]);
        }

        if (kt == qt) {
            #pragma unroll
            for (int r = 0; r < 2; ++r) {
                const int rloc = 16 * warp + g + 8 * r;
                #pragma unroll
                for (int ni = 0; ni < 8; ++ni) {
                    const int cloc = ni * 8 + 2 * t4;
                    if (cloc     > rloc) c[ni][2 * r]     = -INFINITY;
                    if (cloc + 1 > rloc) c[ni][2 * r + 1] = -INFINITY;
                }
            }
        }

        #pragma unroll
        for (int r = 0; r < 2; ++r) {
            float mt = -INFINITY;
            #pragma unroll
            for (int ni = 0; ni < 8; ++ni)
                mt = fmaxf(mt, fmaxf(c[ni][2 * r], c[ni][2 * r + 1]));
            mt = fmaxf(mt, __shfl_xor_sync(0xffffffffu, mt, 1));
            mt = fmaxf(mt, __shfl_xor_sync(0xffffffffu, mt, 2));
            const float mn = fmaxf(m_i[r], mt);
            const float corr = __expf(m_i[r] - mn);
            float rs = 0.f;
            #pragma unroll
            for (int ni = 0; ni < 8; ++ni) {
                float p0 = __expf(c[ni][2 * r]     - mn);
                float p1 = __expf(c[ni][2 * r + 1] - mn);
                rs += p0 + p1;
                *(__half2*)&Ps[(16 * warp + g + 8 * r) * AT_LV + ni * 8 + 2 * t4] =
                    __floats2half2_rn(p0, p1);
            }
            rs += __shfl_xor_sync(0xffffffffu, rs, 1);
            rs += __shfl_xor_sync(0xffffffffu, rs, 2);
            l_i[r] = l_i[r] * corr + rs;
            m_i[r] = mn;
            #pragma unroll
            for (int ni = 0; ni < 16; ++ni) {
                o[ni][2 * r]     *= corr;
                o[ni][2 * r + 1] *= corr;
            }
        }
        __syncwarp();

        const uint32_t vb_base = vs_u +
            (uint32_t)((st * 128 * AT_LV + b_row * AT_LV + b_c8) * 2);
        #pragma unroll
        for (int ks = 0; ks < 4; ++ks) {
            uint32_t af[4], bf[16][2];
            LDSM4(af[0], af[1], af[2], af[3], pa_base + (uint32_t)(ks * 32));
            #pragma unroll
            for (int nj = 0; nj < 8; ++nj)
                LDSM4(bf[2 * nj][0], bf[2 * nj][1], bf[2 * nj + 1][0], bf[2 * nj + 1][1],
                      vb_base + (uint32_t)(nj * 16 * AT_LV * 2 + ks * 32));
            #pragma unroll
            for (int ni = 0; ni < 16; ++ni)
                mma_f16_16n8k16(o[ni], af, bf[ni]);
        }
    }

    #pragma unroll
    for (int r = 0; r < 2; ++r) {
        const float inv = 1.f / l_i[r];
        const int row = qt * 64 + 16 * warp + g + 8 * r;
        __half* obase = g_ctxh + (size_t)(b * Ss + row) * Hh + h * HDd;
        #pragma unroll
        for (int ni = 0; ni < 16; ++ni) {
            const int col = ni * 8 + 2 * t4;
            *(__half2*)&obase[col] = __floats2half2_rn(o[ni][2 * r] * inv,
                                                       o[ni][2 * r + 1] * inv);
        }
    }
}

// ---------------------------------------------------------------------------
extern "C" void kernel_launch(void* const* d_in, const int* in_sizes, int n_in,
                              void* d_out, int out_size) {
    const float* hs  = (const float*)d_in[0];
    const float* res = (const float*)d_in[1];
    const float* Wq  = (const float*)d_in[3];
    const float* Wkv = (const float*)d_in[4];
    const float* Wd  = (const float*)d_in[5];
    const float* bd  = (const float*)d_in[6];
    float* out = (float*)d_out;

    float* qkvp;
    __half *hsh, *wt, *wdt, *ctxh;
    cudaGetSymbolAddress((void**)&qkvp, g_qkv);
    cudaGetSymbolAddress((void**)&hsh,  g_hsh);
    cudaGetSymbolAddress((void**)&wt,   g_wt);
    cudaGetSymbolAddress((void**)&wdt,  g_wdt);
    cudaGetSymbolAddress((void**)&ctxh, g_ctxh);

    cudaFuncSetAttribute(attn_f16_kernel, cudaFuncAttributeMaxDynamicSharedMemorySize, AT_SMEM_BYTES);
    cudaFuncSetAttribute(gemm_f16_kernel, cudaFuncAttributeMaxDynamicSharedMemorySize, GSMEM_BYTES);

    // side stream + fork/join events (static host handles; identical captured
    // work every call — graph-capture-safe cross-stream pattern)
    static cudaStream_t s2 = nullptr;
    static cudaEvent_t evF = nullptr, evWd = nullptr, evQ = nullptr, evP2q = nullptr;
    if (!s2) {
        cudaStreamCreateWithFlags(&s2, cudaStreamNonBlocking);
        cudaEventCreateWithFlags(&evF,   cudaEventDisableTiming);
        cudaEventCreateWithFlags(&evWd,  cudaEventDisableTiming);
        cudaEventCreateWithFlags(&evQ,   cudaEventDisableTiming);
        cudaEventCreateWithFlags(&evP2q, cudaEventDisableTiming);
    }

    // fork: Wd transpose on s2 (its CTAs fill the QKV GEMM drain)
    cudaEventRecord(evF, 0);
    cudaStreamWaitEvent(s2, evF, 0);
    wdtrans_kernel<<<(Hh / 32) * (Hh / 32), 256, 0, s2>>>(Wd);
    cudaEventRecord(evWd, s2);

    // main: prep1 (table + hs fp16 + Wq/Wkv transposes)
    prep1_kernel<<<NB_PREP1, 256>>>(hs, Wq, Wkv);

    // QKV GEMM split: Q columns first, then KV columns
    gemm_f16_kernel<<<dim3(Hh / BN, Mtot / BM), 256, GSMEM_BYTES>>>(
        hsh, wt, qkvp, NQKV, Hh, nullptr, nullptr);
    cudaEventRecord(evQ, 0);

    // s2: RoPE-q (DRAM-bound) overlaps the compute-bound KV GEMM below
    cudaStreamWaitEvent(s2, evQ, 0);
    prep2q_kernel<<<NB_ROPEQ, 256, 0, s2>>>();
    cudaEventRecord(evP2q, s2);

    const int NKV = 2 * KVHh * HDd;   // 2048
    gemm_f16_kernel<<<dim3(NKV / BN, Mtot / BM), 256, GSMEM_BYTES>>>(
        hsh, wt + (size_t)Hh * Hh, qkvp + Hh, NQKV, Hh, nullptr, nullptr);

    // main: RoPE-k + V transpose, then join q branch and run attention
    prep2kv_kernel<<<NB_PREP2KV, 256>>>();
    cudaStreamWaitEvent(0, evP2q, 0);
    attn_f16_kernel<<<dim3(Ss / 64, NHh, Bb), 128, AT_SMEM_BYTES>>>();

    // join Wd branch, dense projection + bias + residual
    cudaStreamWaitEvent(0, evWd, 0);
    gemm_f16_kernel<<<dim3(Hh / BN, Mtot / BM), 256, GSMEM_BYTES>>>(
        ctxh, wdt, out, Hh, Hh, bd, res);
}